// round 17
// baseline (speedup 1.0000x reference)
#include <cuda_runtime.h>
#include <cuda_bf16.h>

// Output[b,s,:] == mean(knowledge, axis=0) for every (b,s):
// top_k with max_chunks == K selects a permutation of ALL knowledge rows,
// so mean(take(knowledge, top_k), axis=1) == mean(knowledge, axis=0).
//
// R16 closed the last micro-lever (STG.256 regressed: +3 serial shfls on
// the critical path for a non-binding store tail). Final model: ~5.6us
// launch floor + ~1us warm work + ±0.3us noise; champions R7/R9 = 6.624.
// This round: R7's champion structure (128 CTAs x 512 threads, 4-way
// group split, ONE __syncthreads) minus its residual costs: branch-free
// store tail and only 3 smem partial reads (own partial kept in-register).

#define E_DIM 512
#define K_ROWS 64
#define THREADS 512            // 4 groups of 128; 128 float4 columns
#define ROWS_PER_CTA 32        // 4096 / 32 = 128 CTAs (~one wave)
#define COLS4 (E_DIM / 4)      // 128 float4 per row

__global__ void __launch_bounds__(THREADS)
fused_mean_broadcast(const float4* __restrict__ knowledge4,
                     float4* __restrict__ out) {
    __shared__ float4 part[4 * COLS4];   // 4 partial sums per column, 8KB

    int t = threadIdx.x;
    int c = t & (COLS4 - 1);   // column 0..127
    int q = t >> 7;            // group 0..3: sums rows [16q, 16q+16)

    // Group q sums 16 rows of its column: 16 independent front-batched
    // loads (warp = full 128B sectors), one exposed memory latency.
    float4 s = make_float4(0.f, 0.f, 0.f, 0.f);
#pragma unroll
    for (int k = 0; k < K_ROWS / 4; ++k) {
        float4 a = knowledge4[(q * (K_ROWS / 4) + k) * COLS4 + c];
        s.x += a.x; s.y += a.y; s.z += a.z; s.w += a.w;
    }
    part[q * COLS4 + c] = s;
    __syncthreads();           // the ONLY barrier

    // Column mean: own partial stays in-register; read the other 3
    // (conflict-free LDS.128, consecutive lanes -> consecutive banks).
    const float inv = 1.0f / (float)K_ROWS;
    float4 m = s;
#pragma unroll
    for (int i = 1; i < 4; ++i) {
        float4 p = part[((q + i) & 3) * COLS4 + c];
        m.x += p.x; m.y += p.y; m.z += p.z; m.w += p.w;
    }
    m.x *= inv; m.y *= inv; m.z *= inv; m.w *= inv;

    // CTA writes 32 identical rows; group q writes rows [8q, 8q+8).
    // Branch-free: 4096 % 32 == 0. 8 coalesced STG.128 per thread.
    int r0 = blockIdx.x * ROWS_PER_CTA + q * (ROWS_PER_CTA / 4);
    size_t base = (size_t)r0 * COLS4 + c;
#pragma unroll
    for (int r = 0; r < ROWS_PER_CTA / 4; ++r) {
        out[base + (size_t)r * COLS4] = m;
    }
}

extern "C" void kernel_launch(void* const* d_in, const int* in_sizes, int n_in,
                              void* d_out, int out_size) {
    // d_in[0]: query_embedding [4,1024,512] f32 (unused — output is query-independent)
    // d_in[1]: knowledge [64,512] f32
    const float* knowledge = (const float*)d_in[1];
    float* out = (float*)d_out;

    int rows = out_size / E_DIM;                 // 4096
    int blocks = rows / ROWS_PER_CTA;            // 128

    fused_mean_broadcast<<<blocks, THREADS>>>(
        reinterpret_cast<const float4*>(knowledge),
        reinterpret_cast<float4*>(out));
}